// round 14
// baseline (speedup 1.0000x reference)
#include <cuda_runtime.h>
#include <cstdint>

// ---------------------------------------------------------------------------
// AlignedMPNN: B=8, N=256, F=128, D=128
// Output: ret [8,256,128] followed by et [8,256,256,128]
// ---------------------------------------------------------------------------

#define Bq 8
#define Nn 256
#define Ff 128
#define Dd 128
#define M_ET (Bq * Nn * Nn)          // 524288
#define NROWS (Bq * (Nn + 1))        // 2056
#define N_TILES2 (M_ET / 256)        // 2048 tiles of 256 rows

// scratch for MPNN chain
__device__ float g_msg1[NROWS * Dd];
__device__ float g_msg2[NROWS * Dd];
__device__ float g_o1[NROWS * Dd];

// ===========================================================================
// helpers
// ===========================================================================
__device__ __forceinline__ uint32_t smem_u32_of(const void* p) {
    uint32_t a;
    asm("{ .reg .u64 t; cvta.to.shared.u64 t, %1; cvt.u32.u64 %0, t; }" : "=r"(a) : "l"(p));
    return a;
}

#define STS128(a0, a1, a2, a3, addr) \
    asm volatile("st.shared.v4.b32 [%0], {%1, %2, %3, %4};" :: "r"(addr), "r"(a0), "r"(a1), "r"(a2), "r"(a3) : "memory")

#define LDS128F(v, addr) \
    asm volatile("ld.shared.v4.f32 {%0, %1, %2, %3}, [%4];" \
        : "=f"((v).x), "=f"((v).y), "=f"((v).z), "=f"((v).w) : "r"(addr))

#define LDSM4(r, addr) \
    asm volatile("ldmatrix.sync.aligned.m8n8.x4.shared.b16 {%0,%1,%2,%3}, [%4];" \
        : "=r"((r)[0]), "=r"((r)[1]), "=r"((r)[2]), "=r"((r)[3]) : "r"(addr))

#define LDSM2(r, addr) \
    asm volatile("ldmatrix.sync.aligned.m8n8.x2.shared.b16 {%0,%1}, [%2];" \
        : "=r"((r)[0]), "=r"((r)[1]) : "r"(addr))

#define MMA_F16(d, a, b) \
    asm volatile("mma.sync.aligned.m16n8k16.row.col.f32.f16.f16.f32 " \
        "{%0,%1,%2,%3}, {%4,%5,%6,%7}, {%8,%9}, {%0,%1,%2,%3};" \
        : "+f"((d)[0]), "+f"((d)[1]), "+f"((d)[2]), "+f"((d)[3]) \
        : "r"((a)[0]), "r"((a)[1]), "r"((a)[2]), "r"((a)[3]), "r"((b)[0]), "r"((b)[1]))

__device__ __forceinline__ void cp_async16(uint32_t dst, const void* src) {
    asm volatile("cp.async.cg.shared.global [%0], [%1], 16;"
                 :: "r"(dst), "l"(__cvta_generic_to_global(src)) : "memory");
}
#define CP_COMMIT() asm volatile("cp.async.commit_group;" ::: "memory")
#define CP_WAIT1()  asm volatile("cp.async.wait_group 1;" ::: "memory")

// f16 tile layout: 64B rows, unit u (0..3, 16B), XOR swizzle. (verified R6+)
#define ASWZ64(r, u) ((uint32_t)((r) * 64 + (((u) ^ (((r) >> 1) & 3)) * 16)))

__device__ __forceinline__ uint32_t cvt2h(float x0, float x1) {
    uint32_t r;
    asm("cvt.rn.f16x2.f32 %0, %1, %2;" : "=r"(r) : "f"(x1), "f"(x0));
    return r;
}

// packed fp32 helpers for the FFMA path
__device__ __forceinline__ void unpack2(unsigned long long v, float& x, float& y) {
    asm("mov.b64 {%0,%1}, %2;" : "=f"(x), "=f"(y) : "l"(v));
}
__device__ __forceinline__ unsigned long long bcast2(float x) {
    unsigned long long r;
    asm("mov.b64 %0, {%1,%1};" : "=l"(r) : "f"(x));
    return r;
}
__device__ __forceinline__ unsigned long long pack2f(float x, float y) {
    unsigned long long r;
    asm("mov.b64 %0, {%1,%2};" : "=l"(r) : "f"(x), "f"(y));
    return r;
}
#define FFMA2(d, a, b) asm("fma.rn.f32x2 %0, %1, %2, %0;" : "+l"(d) : "l"(a), "l"(b))
#define LDS64U(v, addr) asm volatile("ld.shared.b64 %0, [%1];" : "=l"(v) : "r"(addr))
#define LDSV2U64(a, b, addr) \
    asm volatile("ld.shared.v2.b64 {%0,%1}, [%2];" : "=l"(a), "=l"(b) : "r"(addr))

// ===========================================================================
// et GEMM: C[M,128] = A1[M,128k] @ W[0:128,:] + A2[M,128k] @ W[128:256,:] + be
// Dual-pipe: 148 persistent CTAs x 512 threads (16 warps), 1 CTA/SM.
//   warps 0-11 (3/SMSP): f16 mma.sync on cols 0..95   (tensor pipe)
//   warps 12-15 (1/SMSP): packed fp32 FFMA2 on cols 96..127 (fma pipe, exact)
// M-tile 256, k32 chunks. Per-SMSP per chunk: 96 HMMA (~2300cyc) || 1024
// FFMA2 (~2050cyc) -> both pipes busy concurrently.
//
// Pipeline window w: issue cp.async(w+3); [tensor: MMA(w); wait1; cvt(w+1)]
// || [ffma: wait1; cvt(w+1); FFMA(w+1) from f32 stage]; barrier.
// wait_group 1 each window guarantees group w+1 complete in window w-1 for
// every thread, so cross-thread f32-stage reads in window w are ordered by
// the barrier. Stage (w)%3 is last read in window w-1, overwritten by
// issue(w+3) in window w -> safe.
//
// smem (208.5KB):
//   [0      .. 49152)  W f16 cols 0..95: 8 k32-chunks x 6144B, ASWZ64 rows
//   [49152  .. 81920)  W f32 cols 96..127: [k=256][32] floats
//   [81920  .. 114688) A f16: 2 bufs x 16KB (256 rows x 64B), ASWZ64
//   [114688 .. 212992) A f32 stage: 3 x 32KB (256 rows x 128B, XOR units)
//   [212992 .. 213504) bias f32[128]
// ===========================================================================
#define OFF_WF32 49152
#define OFF_F16  81920
#define OFF_F32  114688
#define OFF_BIAS 212992
#define SMEM_ET  213504

__global__ __launch_bounds__(512, 1)
void et_mma_kernel(const float* __restrict__ A1,
                   const float* __restrict__ A2,
                   const float* __restrict__ W,     // [256,128] f32
                   const float* __restrict__ bias,  // [128]
                   float* __restrict__ C)           // [M,128]
{
    extern __shared__ char smem[];
    const uint32_t sb = smem_u32_of(smem);
    const int tid  = threadIdx.x;
    const int lane = tid & 31;
    const int wid  = tid >> 5;

    // ---- one-time W f16 (cols 0..95, frag layout) + W f32 slice + bias ----
    {
        const int n = tid & 127;
        const int g = tid >> 7;                 // 0..3
        if (n < 96) {
#pragma unroll
            for (int t = 0; t < 8; ++t) {
                const int kk = g * 8 + t;       // 16B-unit index 0..31
                const int c  = kk >> 2;
                const int u  = kk & 3;
                float w[8];
#pragma unroll
                for (int j = 0; j < 8; ++j) w[j] = W[(kk * 8 + j) * 128 + n];
                uint32_t p0 = cvt2h(w[0], w[1]);
                uint32_t p1 = cvt2h(w[2], w[3]);
                uint32_t p2 = cvt2h(w[4], w[5]);
                uint32_t p3 = cvt2h(w[6], w[7]);
                STS128(p0, p1, p2, p3, sb + c * 6144 + ASWZ64(n, u));
            }
        }
        for (int idx = tid; idx < 8192; idx += 512)
            ((float*)(smem + OFF_WF32))[idx] = W[(idx >> 5) * 128 + 96 + (idx & 31)];
        if (tid < 128) ((float*)(smem + OFF_BIAS))[tid] = bias[tid];
    }

    // ---- common A staging mapping (2 threads per row) ----
    const int row  = tid >> 1;
    const int half = tid & 1;
    const uint32_t f32row = (uint32_t)(OFF_F32 + row * 128);
    uint32_t fu[4];
#pragma unroll
    for (int q = 0; q < 4; ++q)
        fu[q] = (uint32_t)((((half * 4 + q) ^ (row & 7)) * 16));
    const uint32_t sa0 = (uint32_t)OFF_F16 + ASWZ64(row, half * 2);
    const uint32_t sa1 = (uint32_t)OFF_F16 + ASWZ64(row, half * 2 + 1);
    const int goff = row * 128 + half * 16;

    const int ntiles = (N_TILES2 - blockIdx.x + gridDim.x - 1) / gridDim.x;
    const int G = ntiles * 8;
    const float* bias_s = (const float*)(smem + OFF_BIAS);

    __syncthreads();

    // issue helper (inline): chunk q -> gmem ptr
#define ISSUE_CHUNK(q) do {                                                   \
        if ((q) < G) {                                                        \
            const int _t = blockIdx.x + ((q) >> 3) * gridDim.x;               \
            const int _c = (q) & 7;                                           \
            const float* _b = (_c < 4) ? A1 : A2;                             \
            const float* _p = _b + (size_t)_t * 32768 + goff + (_c & 3) * 32; \
            const uint32_t _d = sb + f32row + ((q) % 3) * 32768;              \
            cp_async16(_d + fu[0], _p);                                       \
            cp_async16(_d + fu[1], _p + 4);                                   \
            cp_async16(_d + fu[2], _p + 8);                                   \
            cp_async16(_d + fu[3], _p + 12);                                  \
        }                                                                     \
        CP_COMMIT();                                                          \
    } while (0)

#define CONVERT_CHUNK(q) do {                                                 \
        const uint32_t _s = sb + f32row + ((q) % 3) * 32768;                  \
        float4 _v0, _v1, _v2, _v3;                                            \
        LDS128F(_v0, _s + fu[0]);                                             \
        LDS128F(_v1, _s + fu[1]);                                             \
        LDS128F(_v2, _s + fu[2]);                                             \
        LDS128F(_v3, _s + fu[3]);                                             \
        uint32_t _p0 = cvt2h(_v0.x, _v0.y), _p1 = cvt2h(_v0.z, _v0.w);        \
        uint32_t _p2 = cvt2h(_v1.x, _v1.y), _p3 = cvt2h(_v1.z, _v1.w);        \
        uint32_t _p4 = cvt2h(_v2.x, _v2.y), _p5 = cvt2h(_v2.z, _v2.w);        \
        uint32_t _p6 = cvt2h(_v3.x, _v3.y), _p7 = cvt2h(_v3.z, _v3.w);        \
        const uint32_t _fb = sb + ((q) & 1) * 16384;                          \
        STS128(_p0, _p1, _p2, _p3, _fb + sa0);                                \
        STS128(_p4, _p5, _p6, _p7, _fb + sa1);                                \
    } while (0)

    // ---- prologue: issue 0,1,2; convert 0; ffma 0 ----
    ISSUE_CHUNK(0);
    ISSUE_CHUNK(1);
    ISSUE_CHUNK(2);
    CP_WAIT1();
    __syncthreads();            // groups 0,1 globally visible

    if (wid < 12) {
        // ======================= TENSOR ROLE =======================
        const int warpM = wid & 3;       // 0..3 -> rows warpM*64
        const int warpN = wid >> 2;      // 0..2 -> cols warpN*32

        const int mat  = lane >> 3;
        const int row0 = warpM * 64 + (mat & 1) * 8 + (lane & 7);
        const int ah   = mat >> 1;
        const int xr   = (row0 >> 1) & 3;
        uint32_t aoffs[2];
#pragma unroll
        for (int s = 0; s < 2; ++s)
            aoffs[s] = (uint32_t)(row0 * 64 + (((2 * s + ah) ^ xr) * 16));

        const int ls = lane & 15;
        const int n0 = warpN * 32 + (ls & 7);
        const int ub = ls >> 3;
        const int xn = (n0 >> 1) & 3;
        uint32_t boffs[2];
#pragma unroll
        for (int s = 0; s < 2; ++s)
            boffs[s] = (uint32_t)(n0 * 64 + (((2 * s + ub) ^ xn) * 16));

        float2 biasv[4];
#pragma unroll
        for (int nt = 0; nt < 4; ++nt)
            biasv[nt] = *(const float2*)&bias_s[warpN * 32 + nt * 8 + (lane & 3) * 2];

        CONVERT_CHUNK(0);
        __syncthreads();        // end of prologue (buf0 ready)

        int mytile = blockIdx.x;
        float acc[4][4][4];
#pragma unroll
        for (int mt = 0; mt < 4; ++mt)
#pragma unroll
            for (int nt = 0; nt < 4; ++nt) {
                acc[mt][nt][0] = biasv[nt].x; acc[mt][nt][1] = biasv[nt].y;
                acc[mt][nt][2] = biasv[nt].x; acc[mt][nt][3] = biasv[nt].y;
            }

#pragma unroll 1
        for (int w = 0; w < G; ++w) {
            ISSUE_CHUNK(w + 3);

            // MMA chunk w
            const uint32_t wb = sb + (uint32_t)((w & 7) * 6144);
            const uint32_t ab = sb + OFF_F16 + (w & 1) * 16384;
#pragma unroll
            for (int s = 0; s < 2; ++s) {
                uint32_t Av[4][4], Bv[4][2];
#pragma unroll
                for (int mt = 0; mt < 4; ++mt) LDSM4(Av[mt], ab + aoffs[s] + mt * 1024);
#pragma unroll
                for (int nt = 0; nt < 4; ++nt) LDSM2(Bv[nt], wb + boffs[s] + nt * 512);
#pragma unroll
                for (int mt = 0; mt < 4; ++mt)
#pragma unroll
                    for (int nt = 0; nt < 4; ++nt) MMA_F16(acc[mt][nt], Av[mt], Bv[nt]);
            }

            if ((w & 7) == 7) {
                const size_t m0 = (size_t)mytile * 256;
#pragma unroll
                for (int mt = 0; mt < 4; ++mt) {
                    const size_t r0 = m0 + warpM * 64 + mt * 16 + (lane >> 2);
#pragma unroll
                    for (int nt = 0; nt < 4; ++nt) {
                        const int col = warpN * 32 + nt * 8 + (lane & 3) * 2;
                        *(float2*)&C[r0 * 128 + col]       = make_float2(acc[mt][nt][0], acc[mt][nt][1]);
                        *(float2*)&C[(r0 + 8) * 128 + col] = make_float2(acc[mt][nt][2], acc[mt][nt][3]);
                    }
                }
                mytile += gridDim.x;
#pragma unroll
                for (int mt = 0; mt < 4; ++mt)
#pragma unroll
                    for (int nt = 0; nt < 4; ++nt) {
                        acc[mt][nt][0] = biasv[nt].x; acc[mt][nt][1] = biasv[nt].y;
                        acc[mt][nt][2] = biasv[nt].x; acc[mt][nt][3] = biasv[nt].y;
                    }
            }

            CP_WAIT1();
            if (w + 1 < G) CONVERT_CHUNK(w + 1);
            __syncthreads();
        }
    } else {
        // ======================= FFMA ROLE =======================
        const int fwid = wid - 12;       // 0..3 -> rows fwid*64 (on SMSP wid&3)
        const int tr = lane >> 2;        // 0..7  -> 8 rows
        const int tc = lane & 3;         // 0..3  -> 8 cols (of 32)

        uint32_t arow[8];                // rotated row byte offsets (stage-rel)
        int xi[8];
#pragma unroll
        for (int i = 0; i < 8; ++i) {
            const int rot = (i + tr) & 7;
            arow[i] = (uint32_t)((fwid * 64 + tr * 8 + rot) * 128);
            xi[i]   = rot;
        }
        const uint32_t wcb = sb + OFF_WF32 + tc * 32;   // + k*128

        unsigned long long bini[4];
#pragma unroll
        for (int j = 0; j < 4; ++j)
            bini[j] = pack2f(bias_s[96 + tc * 8 + 2 * j], bias_s[96 + tc * 8 + 2 * j + 1]);

        unsigned long long acc[8][4];
#pragma unroll
        for (int i = 0; i < 8; ++i)
#pragma unroll
            for (int j = 0; j < 4; ++j) acc[i][j] = bini[j];

        // ffma compute of chunk q
#define FFMA_CHUNK(q) do {                                                    \
            const uint32_t _st = sb + OFF_F32 + ((q) % 3) * 32768;            \
            const uint32_t _wk = wcb + (uint32_t)(((q) & 7) * 32) * 128;      \
            _Pragma("unroll 4")                                               \
            for (int k2 = 0; k2 < 16; ++k2) {                                 \
                const int kk = 2 * k2;                                        \
                unsigned long long w0a, w0b, w0c, w0d, w1a, w1b, w1c, w1d;    \
                LDSV2U64(w0a, w0b, _wk + kk * 128);                           \
                LDSV2U64(w0c, w0d, _wk + kk * 128 + 16);                      \
                LDSV2U64(w1a, w1b, _wk + kk * 128 + 128);                     \
                LDSV2U64(w1c, w1d, _wk + kk * 128 + 144);                     \
                _Pragma("unroll")                                             \
                for (int i = 0; i < 8; ++i) {                                 \
                    unsigned long long a01;                                   \
                    const uint32_t au = _st + arow[i]                         \
                        + ((((kk >> 2) ^ xi[i]) & 7) * 16) + ((kk & 3) * 4);  \
                    LDS64U(a01, au);                                          \
                    float a0, a1;                                             \
                    unpack2(a01, a0, a1);                                     \
                    unsigned long long a0d = bcast2(a0), a1d = bcast2(a1);    \
                    FFMA2(acc[i][0], a0d, w0a); FFMA2(acc[i][1], a0d, w0b);   \
                    FFMA2(acc[i][2], a0d, w0c); FFMA2(acc[i][3], a0d, w0d);   \
                    FFMA2(acc[i][0], a1d, w1a); FFMA2(acc[i][1], a1d, w1b);   \
                    FFMA2(acc[i][2], a1d, w1c); FFMA2(acc[i][3], a1d, w1d);   \
                }                                                             \
            }                                                                 \
        } while (0)

        CONVERT_CHUNK(0);
        FFMA_CHUNK(0);
        __syncthreads();        // end of prologue

        int mytile = blockIdx.x;
#pragma unroll 1
        for (int w = 0; w < G; ++w) {
            ISSUE_CHUNK(w + 3);
            CP_WAIT1();
            if (w + 1 < G) CONVERT_CHUNK(w + 1);

            if (((w + 1) & 7) == 0) {
                // store completed tile
                const size_t m0 = (size_t)mytile * 256;
#pragma unroll
                for (int i = 0; i < 8; ++i) {
                    const size_t r = m0 + fwid * 64 + tr * 8 + ((i + tr) & 7);
                    float f[8];
                    unpack2(acc[i][0], f[0], f[1]);
                    unpack2(acc[i][1], f[2], f[3]);
                    unpack2(acc[i][2], f[4], f[5]);
                    unpack2(acc[i][3], f[6], f[7]);
                    float* dst = &C[r * 128 + 96 + tc * 8];
                    *(float4*)dst       = make_float4(f[0], f[1], f[2], f[3]);
                    *(float4*)(dst + 4) = make_float4(f[4], f[5], f[6], f[7]);
                }
                mytile += gridDim.x;
#pragma unroll
                for (int i = 0; i < 8; ++i)
#pragma unroll
                    for (int j = 0; j < 4; ++j) acc[i][j] = bini[j];
            }

            if (w + 1 < G) FFMA_CHUNK(w + 1);
            __syncthreads();
        }
#undef FFMA_CHUNK
    }
#undef ISSUE_CHUNK
#undef CONVERT_CHUNK
}

// ===========================================================================
// Kernel 2: msg1/msg2/o1 = nt @ {W_m1,W_m2,W_o1} + bias.
// ===========================================================================
__global__ __launch_bounds__(512)
void msgs_gemm_kernel(const float* __restrict__ node,
                      const float* __restrict__ hidden,
                      const float* __restrict__ Wm1, const float* __restrict__ bm1,
                      const float* __restrict__ Wm2, const float* __restrict__ bm2,
                      const float* __restrict__ Wo1, const float* __restrict__ bo1)
{
    __shared__ float s[8][2 * Ff];
    __shared__ float part[3][3][8][128];
    const int r0  = blockIdx.x * 8;
    const int tid = threadIdx.x;
    const int col = tid & 127;
    const int kq  = tid >> 7;

    for (int t = tid; t < 8 * 256; t += 512) {
        const int r = t >> 8, k = t & 255;
        const int rowi = r0 + r;
        const int b = rowi / (Nn + 1);
        const int i = rowi % (Nn + 1);
        float v = 0.f;
        if (i < Nn)
            v = (k < Ff) ? node[(b * Nn + i) * Ff + k]
                         : hidden[(b * Nn + i) * Ff + (k - Ff)];
        s[r][k] = v;
    }
    __syncthreads();

    float a1[8], a2[8], a3[8];
#pragma unroll
    for (int r = 0; r < 8; ++r) { a1[r] = 0.f; a2[r] = 0.f; a3[r] = 0.f; }

    const int kbase = kq * 64;
#pragma unroll 4
    for (int kk = 0; kk < 64; ++kk) {
        const int k = kbase + kk;
        const float w1 = Wm1[k * Dd + col];
        const float w2 = Wm2[k * Dd + col];
        const float w3 = Wo1[k * Dd + col];
#pragma unroll
        for (int r = 0; r < 8; ++r) {
            const float sv = s[r][k];
            a1[r] = fmaf(sv, w1, a1[r]);
            a2[r] = fmaf(sv, w2, a2[r]);
            a3[r] = fmaf(sv, w3, a3[r]);
        }
    }

    if (kq) {
#pragma unroll
        for (int r = 0; r < 8; ++r) {
            part[kq - 1][0][r][col] = a1[r];
            part[kq - 1][1][r][col] = a2[r];
            part[kq - 1][2][r][col] = a3[r];
        }
    }
    __syncthreads();

    if (kq == 0) {
        const float bb1 = bm1[col], bb2 = bm2[col], bb3 = bo1[col];
#pragma unroll
        for (int r = 0; r < 8; ++r) {
            float o1 = a1[r] + bb1, o2 = a2[r] + bb2, o3 = a3[r] + bb3;
#pragma unroll
            for (int q = 0; q < 3; ++q) {
                o1 += part[q][0][r][col];
                o2 += part[q][1][r][col];
                o3 += part[q][2][r][col];
            }
            const int rowi = r0 + r;
            g_msg1[rowi * Dd + col] = o1;
            g_msg2[rowi * Dd + col] = o2;
            g_o1[rowi * Dd + col]   = o3;
        }
    }
}

// ===========================================================================
// Kernel 3 (fused): masked max + add msg1, then ret = o1 + msgs @ W_o2 + b_o2
// ===========================================================================
__global__ __launch_bounds__(256)
void maxfinal_kernel(const int* __restrict__ adj,
                     const float* __restrict__ Wo2,
                     const float* __restrict__ bo2,
                     float* __restrict__ out)      // [B*N,128]
{
    __shared__ int mask[Nn];
    __shared__ float red[2][4][128];
    __shared__ float ms[4][128];
    __shared__ float pg[4][128];
    const int blk = blockIdx.x;
    const int b   = blk >> 6;
    const int j0  = (blk & 63) * 4;
    const int tid = threadIdx.x;
    const int d   = tid & 127;
    const int ih  = tid >> 7;

    {
        const int* p = adj + ((size_t)(b * Nn + tid) * Nn + j0);
        const int4 a = *(const int4*)p;
        mask[tid] = (a.x > 0) | ((a.y > 0) << 1) | ((a.z > 0) << 2) | ((a.w > 0) << 3);
    }
    __syncthreads();

    const float* m2 = g_msg2 + (size_t)(b * (Nn + 1)) * Dd + d;
    const float vv = m2[Nn * Dd];
    float vj[4] = {vv, vv, vv, vv};

#pragma unroll 4
    for (int ii = 0; ii < 128; ++ii) {
        const int i = ih * 128 + ii;
        const float x = m2[i * Dd];
        const int mk = mask[i];
#pragma unroll
        for (int q = 0; q < 4; ++q)
            if (mk & (1 << q)) vj[q] = fmaxf(vj[q], x);
    }
#pragma unroll
    for (int q = 0; q < 4; ++q) red[ih][q][d] = vj[q];
    __syncthreads();

    if (ih == 0) {
#pragma unroll
        for (int q = 0; q < 4; ++q)
            ms[q][d] = g_msg1[(size_t)(b * (Nn + 1) + j0 + q) * Dd + d]
                     + fmaxf(red[0][q][d], red[1][q][d]);
    }
    __syncthreads();

    float acc[4] = {0.f, 0.f, 0.f, 0.f};
    const int kb = ih * 64;
#pragma unroll 4
    for (int kk = 0; kk < 64; ++kk) {
        const int k = kb + kk;
        const float w = Wo2[k * Dd + d];
#pragma unroll
        for (int q = 0; q < 4; ++q) acc[q] = fmaf(ms[q][k], w, acc[q]);
    }
    if (ih) {
#pragma unroll
        for (int q = 0; q < 4; ++q) pg[q][d] = acc[q];
    }
    __syncthreads();
    if (!ih) {
        const float bb = bo2[d];
#pragma unroll
        for (int q = 0; q < 4; ++q)
            out[(size_t)(b * Nn + j0 + q) * Dd + d] =
                acc[q] + pg[q][d] + g_o1[(size_t)(b * (Nn + 1) + j0 + q) * Dd + d] + bb;
    }
}

// ===========================================================================
extern "C" void kernel_launch(void* const* d_in, const int* in_sizes, int n_in,
                              void* d_out, int out_size)
{
    const float* node_fts = (const float*)d_in[0];
    const float* edge_fts = (const float*)d_in[1];
    const int*   adj_mat  = (const int*)d_in[3];
    const float* hidden   = (const float*)d_in[4];
    const float* e_hidden = (const float*)d_in[5];
    const float* We   = (const float*)d_in[6];
    const float* be   = (const float*)d_in[7];
    const float* W_m1 = (const float*)d_in[8];
    const float* b_m1 = (const float*)d_in[9];
    const float* W_m2 = (const float*)d_in[10];
    const float* b_m2 = (const float*)d_in[11];
    const float* W_o1 = (const float*)d_in[12];
    const float* b_o1 = (const float*)d_in[13];
    const float* W_o2 = (const float*)d_in[14];
    const float* b_o2 = (const float*)d_in[15];

    float* ret_out = (float*)d_out;
    float* et_out  = (float*)d_out + Bq * Nn * Dd;

    static cudaStream_t s_chain = nullptr;
    static cudaEvent_t ev_fork = nullptr, ev_join = nullptr;
    if (!s_chain) {
        cudaStreamCreateWithFlags(&s_chain, cudaStreamNonBlocking);
        cudaEventCreateWithFlags(&ev_fork, cudaEventDisableTiming);
        cudaEventCreateWithFlags(&ev_join, cudaEventDisableTiming);
        cudaFuncSetAttribute(et_mma_kernel, cudaFuncAttributeMaxDynamicSharedMemorySize, SMEM_ET);
    }

    // fork: MPNN chain runs concurrently with the big et GEMM
    cudaEventRecord(ev_fork, 0);
    cudaStreamWaitEvent(s_chain, ev_fork, 0);
    msgs_gemm_kernel<<<NROWS / 8, 512, 0, s_chain>>>(node_fts, hidden,
                                                     W_m1, b_m1, W_m2, b_m2, W_o1, b_o1);
    maxfinal_kernel<<<Bq * Nn / 4, 256, 0, s_chain>>>(adj_mat, W_o2, b_o2, ret_out);
    cudaEventRecord(ev_join, s_chain);

    // et GEMM (dual-pipe: tensor f16 cols 0..95 + packed-fp32 FFMA cols 96..127)
    et_mma_kernel<<<148, 512, SMEM_ET>>>(edge_fts, e_hidden, We, be, et_out);

    // join
    cudaStreamWaitEvent(0, ev_join, 0);
}

// round 15
// speedup vs baseline: 1.9148x; 1.9148x over previous
#include <cuda_runtime.h>
#include <cstdint>

// ---------------------------------------------------------------------------
// AlignedMPNN: B=8, N=256, F=128, D=128
// Output: ret [8,256,128] followed by et [8,256,256,128]
// ---------------------------------------------------------------------------

#define Bq 8
#define Nn 256
#define Ff 128
#define Dd 128
#define M_ET (Bq * Nn * Nn)          // 524288
#define NROWS (Bq * (Nn + 1))        // 2056
#define N_TILES2 (M_ET / 256)        // 2048 tiles of 256 rows

// scratch for MPNN chain
__device__ float g_msg1[NROWS * Dd];
__device__ float g_msg2[NROWS * Dd];
__device__ float g_o1[NROWS * Dd];

// ===========================================================================
// helpers
// ===========================================================================
__device__ __forceinline__ uint32_t smem_u32_of(const void* p) {
    uint32_t a;
    asm("{ .reg .u64 t; cvta.to.shared.u64 t, %1; cvt.u32.u64 %0, t; }" : "=r"(a) : "l"(p));
    return a;
}

#define STS128(a0, a1, a2, a3, addr) \
    asm volatile("st.shared.v4.b32 [%0], {%1, %2, %3, %4};" :: "r"(addr), "r"(a0), "r"(a1), "r"(a2), "r"(a3) : "memory")

#define LDS128F(v, addr) \
    asm volatile("ld.shared.v4.f32 {%0, %1, %2, %3}, [%4];" \
        : "=f"((v).x), "=f"((v).y), "=f"((v).z), "=f"((v).w) : "r"(addr))

#define LDSM4(r, addr) \
    asm volatile("ldmatrix.sync.aligned.m8n8.x4.shared.b16 {%0,%1,%2,%3}, [%4];" \
        : "=r"((r)[0]), "=r"((r)[1]), "=r"((r)[2]), "=r"((r)[3]) : "r"(addr))

#define LDSM2(r, addr) \
    asm volatile("ldmatrix.sync.aligned.m8n8.x2.shared.b16 {%0,%1}, [%2];" \
        : "=r"((r)[0]), "=r"((r)[1]) : "r"(addr))

#define MMA_F16(d, a, b) \
    asm volatile("mma.sync.aligned.m16n8k16.row.col.f32.f16.f16.f32 " \
        "{%0,%1,%2,%3}, {%4,%5,%6,%7}, {%8,%9}, {%0,%1,%2,%3};" \
        : "+f"((d)[0]), "+f"((d)[1]), "+f"((d)[2]), "+f"((d)[3]) \
        : "r"((a)[0]), "r"((a)[1]), "r"((a)[2]), "r"((a)[3]), "r"((b)[0]), "r"((b)[1]))

__device__ __forceinline__ void cp_async16(uint32_t dst, const void* src) {
    asm volatile("cp.async.cg.shared.global [%0], [%1], 16;"
                 :: "r"(dst), "l"(__cvta_generic_to_global(src)) : "memory");
}
#define CP_COMMIT() asm volatile("cp.async.commit_group;" ::: "memory")
#define CP_WAIT1()  asm volatile("cp.async.wait_group 1;" ::: "memory")

// f16 tile layout: 64B rows, unit u (0..3, 16B), XOR swizzle. (verified R6+)
#define ASWZ64(r, u) ((uint32_t)((r) * 64 + (((u) ^ (((r) >> 1) & 3)) * 16)))

// pack two f32 -> f16x2 (x0 in low half)
__device__ __forceinline__ uint32_t cvt2h(float x0, float x1) {
    uint32_t r;
    asm("cvt.rn.f16x2.f32 %0, %1, %2;" : "=r"(r) : "f"(x1), "f"(x0));
    return r;
}

// ===========================================================================
// et GEMM: C[M,128] = A1[M,128k] @ W[0:128,:] + A2[M,128k] @ W[128:256,:] + be
// fp16 single-term mma.sync; 148 persistent CTAs x 512 threads, 1 CTA/SM.
// M-tile 256, warp grid 4x4 (64x32/warp).
//
// k64 REGIONS (2 k32 chunks per region, ONE barrier per region, 4 per tile):
//   region: early-issue(qb+4) -> MMA 64/warp (chunks qb,qb+1 from f16 buf)
//           -> wait_group 1 -> convert qb+2,qb+3 -> f16 buf^1
//           -> late-issue(qb+5) -> __syncthreads
// Ring-3 f32 stages, per-thread self-consume (each thread cp.asyncs and
// LDSes only its own 16B units), so the late-issue rewrite of a stage this
// thread just read is ordered by the in-order per-thread L1 queue.
// Half the barriers / converts-batches of R8 per unit work -> targets the
// measured ~3300cyc fixed per-region cost.
//
// smem (224KB):
//   [0      .. 65536)  W f16: 8 k32-chunks (8KB each), ASWZ64 rows
//   [65536  .. 131072) A f16: 2 region bufs x 32KB (2 halves x 16KB each)
//   [131072 .. 229376) A f32 stage: 3 x 32KB (256 rows x 128B, XOR units)
// ===========================================================================
#define OFF_F16 65536
#define OFF_F32 131072
#define SMEM_ET 229376

__global__ __launch_bounds__(512, 1)
void et_mma_kernel(const float* __restrict__ A1,
                   const float* __restrict__ A2,
                   const float* __restrict__ W,     // [256,128] f32
                   const float* __restrict__ bias,  // [128]
                   float* __restrict__ C)           // [M,128]
{
    extern __shared__ char smem[];
    const uint32_t sb = smem_u32_of(smem);
    const int tid   = threadIdx.x;
    const int lane  = tid & 31;
    const int wid   = tid >> 5;
    const int warpM = wid >> 2;      // 0..3
    const int warpN = wid & 3;       // 0..3

    // ---- one-time W conversion into resident smem (fp16, [n][k]) ----
    {
        const int n = tid & 127;
        const int g = tid >> 7;                 // 0..3
#pragma unroll
        for (int t = 0; t < 8; ++t) {
            const int kk = g * 8 + t;           // 8-k unit index 0..31
            const int c  = kk >> 2;
            const int u  = kk & 3;
            float w[8];
#pragma unroll
            for (int j = 0; j < 8; ++j) w[j] = W[(kk * 8 + j) * 128 + n];
            uint32_t p0 = cvt2h(w[0], w[1]);
            uint32_t p1 = cvt2h(w[2], w[3]);
            uint32_t p2 = cvt2h(w[4], w[5]);
            uint32_t p3 = cvt2h(w[6], w[7]);
            STS128(p0, p1, p2, p3, sb + c * 8192 + ASWZ64(n, u));
        }
    }

    // ---- per-thread invariant addressing ----
    const int mat  = lane >> 3;
    const int row0 = warpM * 64 + (mat & 1) * 8 + (lane & 7);
    const int ah   = mat >> 1;
    const int xr   = (row0 >> 1) & 3;
    uint32_t aoffs[2];
#pragma unroll
    for (int s = 0; s < 2; ++s)
        aoffs[s] = (uint32_t)(row0 * 64 + (((2 * s + ah) ^ xr) * 16));

    const int ls = lane & 15;
    const int n0 = warpN * 32 + (ls & 7);
    const int ub = ls >> 3;
    const int xn = (n0 >> 1) & 3;
    uint32_t boffs[2];
#pragma unroll
    for (int s = 0; s < 2; ++s)
        boffs[s] = (uint32_t)(n0 * 64 + (((2 * s + ub) ^ xn) * 16));

    float2 biasv[4];
#pragma unroll
    for (int nt = 0; nt < 4; ++nt)
        biasv[nt] = *(const float2*)&bias[warpN * 32 + nt * 8 + (lane & 3) * 2];

    // A staging: 2 threads per row; each thread owns 4 x 16B units of its row.
    const int row  = tid >> 1;
    const int half = tid & 1;
    const uint32_t f32row = (uint32_t)(OFF_F32 + row * 128);
    uint32_t fu[4];
#pragma unroll
    for (int q = 0; q < 4; ++q)
        fu[q] = (uint32_t)((((half * 4 + q) ^ (row & 7)) * 16));
    const uint32_t sa0 = ASWZ64(row, half * 2);        // within a 16KB half
    const uint32_t sa1 = ASWZ64(row, half * 2 + 1);
    const int goff = row * 128 + half * 16;

    __syncthreads();

    // chunk q (global, k32): tile = blockIdx.x + (q>>3)*gridDim.x, c = q&7
#define ISSUE(q) do {                                                         \
        const int _t = blockIdx.x + ((q) >> 3) * gridDim.x;                   \
        if (_t < N_TILES2) {                                                  \
            const int _c = (q) & 7;                                           \
            const float* _b = (_c < 4) ? A1 : A2;                             \
            const float* _p = _b + (size_t)_t * 32768 + goff + (_c & 3) * 32; \
            const uint32_t _d = sb + f32row + ((q) % 3) * 32768;              \
            cp_async16(_d + fu[0], _p);                                       \
            cp_async16(_d + fu[1], _p + 4);                                   \
            cp_async16(_d + fu[2], _p + 8);                                   \
            cp_async16(_d + fu[3], _p + 12);                                  \
        }                                                                     \
        CP_COMMIT();                                                          \
    } while (0)

    // convert chunk q (f32 stage -> f16 dst half base, dstbase = smem offset)
#define CONVERT(q, dstbase) do {                                              \
        const uint32_t _s = sb + f32row + ((q) % 3) * 32768;                  \
        float4 _v0, _v1, _v2, _v3;                                            \
        LDS128F(_v0, _s + fu[0]);                                             \
        LDS128F(_v1, _s + fu[1]);                                             \
        LDS128F(_v2, _s + fu[2]);                                             \
        LDS128F(_v3, _s + fu[3]);                                             \
        uint32_t _p0 = cvt2h(_v0.x, _v0.y), _p1 = cvt2h(_v0.z, _v0.w);        \
        uint32_t _p2 = cvt2h(_v1.x, _v1.y), _p3 = cvt2h(_v1.z, _v1.w);        \
        uint32_t _p4 = cvt2h(_v2.x, _v2.y), _p5 = cvt2h(_v2.z, _v2.w);        \
        uint32_t _p6 = cvt2h(_v3.x, _v3.y), _p7 = cvt2h(_v3.z, _v3.w);        \
        const uint32_t _fb = sb + (dstbase);                                  \
        STS128(_p0, _p1, _p2, _p3, _fb + sa0);                                \
        STS128(_p4, _p5, _p6, _p7, _fb + sa1);                                \
    } while (0)

    // ---- prologue: stages 0,1,2; convert chunks 0,1 -> region buf 0 ----
    ISSUE(0);
    ISSUE(1);
    ISSUE(2);
    CP_WAIT1();                              // chunks 0,1 resident
    CONVERT(0, OFF_F16 + 0);
    CONVERT(1, OFF_F16 + 16384);
    ISSUE(3);                                // stage 0, after this thread read it
    __syncthreads();

    int tile = blockIdx.x;
    int tl = 0;                              // local tile counter

    while (tile < N_TILES2) {
        float acc[4][4][4];
#pragma unroll
        for (int mt = 0; mt < 4; ++mt)
#pragma unroll
            for (int nt = 0; nt < 4; ++nt) {
                acc[mt][nt][0] = biasv[nt].x; acc[mt][nt][1] = biasv[nt].y;
                acc[mt][nt][2] = biasv[nt].x; acc[mt][nt][3] = biasv[nt].y;
            }

#pragma unroll 1
        for (int r = 0; r < 4; ++r) {        // k64 regions
            const int qb = tl * 8 + r * 2;   // base chunk of this region

            ISSUE(qb + 4);                   // stage (qb+1)%3 (read last region)

            // MMA: 4 k16 steps over chunks qb (half0) and qb+1 (half1)
            const uint32_t ab = sb + OFF_F16 + (uint32_t)((r & 1) * 32768);
#pragma unroll
            for (int s = 0; s < 4; ++s) {
                const int cc = r * 2 + (s >> 1);        // W k32-chunk index
                const uint32_t wb = sb + (uint32_t)(cc * 8192);
                const uint32_t abh = ab + (uint32_t)((s >> 1) * 16384);
                uint32_t Av[4][4], Bv[4][2];
#pragma unroll
                for (int mt = 0; mt < 4; ++mt) LDSM4(Av[mt], abh + aoffs[s & 1] + mt * 1024);
#pragma unroll
                for (int nt = 0; nt < 4; ++nt) LDSM2(Bv[nt], wb + boffs[s & 1] + nt * 512);
#pragma unroll
                for (int mt = 0; mt < 4; ++mt)
#pragma unroll
                    for (int nt = 0; nt < 4; ++nt) MMA_F16(acc[mt][nt], Av[mt], Bv[nt]);
            }

            // stage data for next region
            CP_WAIT1();                      // chunks <= qb+3 resident
            const uint32_t dst = (uint32_t)(OFF_F16 + (((r + 1) & 1) * 32768));
            CONVERT(qb + 2, dst);
            CONVERT(qb + 3, dst + 16384);
            ISSUE(qb + 5);                   // stage (qb+2)%3, just read above
            __syncthreads();
        }

        // epilogue: direct STG (32B-sector aligned float2 stores)
        const size_t m0 = (size_t)tile * 256;
#pragma unroll
        for (int mt = 0; mt < 4; ++mt) {
            const size_t r0 = m0 + warpM * 64 + mt * 16 + (lane >> 2);
#pragma unroll
            for (int nt = 0; nt < 4; ++nt) {
                const int col = warpN * 32 + nt * 8 + (lane & 3) * 2;
                *(float2*)&C[r0 * 128 + col]       = make_float2(acc[mt][nt][0], acc[mt][nt][1]);
                *(float2*)&C[(r0 + 8) * 128 + col] = make_float2(acc[mt][nt][2], acc[mt][nt][3]);
            }
        }
        tile += gridDim.x;
        ++tl;
    }
#undef ISSUE
#undef CONVERT
}

// ===========================================================================
// Kernel 2: msg1/msg2/o1 = nt @ {W_m1,W_m2,W_o1} + bias.
// ===========================================================================
__global__ __launch_bounds__(512)
void msgs_gemm_kernel(const float* __restrict__ node,
                      const float* __restrict__ hidden,
                      const float* __restrict__ Wm1, const float* __restrict__ bm1,
                      const float* __restrict__ Wm2, const float* __restrict__ bm2,
                      const float* __restrict__ Wo1, const float* __restrict__ bo1)
{
    __shared__ float s[8][2 * Ff];
    __shared__ float part[3][3][8][128];
    const int r0  = blockIdx.x * 8;
    const int tid = threadIdx.x;
    const int col = tid & 127;
    const int kq  = tid >> 7;

    for (int t = tid; t < 8 * 256; t += 512) {
        const int r = t >> 8, k = t & 255;
        const int rowi = r0 + r;
        const int b = rowi / (Nn + 1);
        const int i = rowi % (Nn + 1);
        float v = 0.f;
        if (i < Nn)
            v = (k < Ff) ? node[(b * Nn + i) * Ff + k]
                         : hidden[(b * Nn + i) * Ff + (k - Ff)];
        s[r][k] = v;
    }
    __syncthreads();

    float a1[8], a2[8], a3[8];
#pragma unroll
    for (int r = 0; r < 8; ++r) { a1[r] = 0.f; a2[r] = 0.f; a3[r] = 0.f; }

    const int kbase = kq * 64;
#pragma unroll 4
    for (int kk = 0; kk < 64; ++kk) {
        const int k = kbase + kk;
        const float w1 = Wm1[k * Dd + col];
        const float w2 = Wm2[k * Dd + col];
        const float w3 = Wo1[k * Dd + col];
#pragma unroll
        for (int r = 0; r < 8; ++r) {
            const float sv = s[r][k];
            a1[r] = fmaf(sv, w1, a1[r]);
            a2[r] = fmaf(sv, w2, a2[r]);
            a3[r] = fmaf(sv, w3, a3[r]);
        }
    }

    if (kq) {
#pragma unroll
        for (int r = 0; r < 8; ++r) {
            part[kq - 1][0][r][col] = a1[r];
            part[kq - 1][1][r][col] = a2[r];
            part[kq - 1][2][r][col] = a3[r];
        }
    }
    __syncthreads();

    if (kq == 0) {
        const float bb1 = bm1[col], bb2 = bm2[col], bb3 = bo1[col];
#pragma unroll
        for (int r = 0; r < 8; ++r) {
            float o1 = a1[r] + bb1, o2 = a2[r] + bb2, o3 = a3[r] + bb3;
#pragma unroll
            for (int q = 0; q < 3; ++q) {
                o1 += part[q][0][r][col];
                o2 += part[q][1][r][col];
                o3 += part[q][2][r][col];
            }
            const int rowi = r0 + r;
            g_msg1[rowi * Dd + col] = o1;
            g_msg2[rowi * Dd + col] = o2;
            g_o1[rowi * Dd + col]   = o3;
        }
    }
}

// ===========================================================================
// Kernel 3 (fused): masked max + add msg1, then ret = o1 + msgs @ W_o2 + b_o2
// ===========================================================================
__global__ __launch_bounds__(256)
void maxfinal_kernel(const int* __restrict__ adj,
                     const float* __restrict__ Wo2,
                     const float* __restrict__ bo2,
                     float* __restrict__ out)      // [B*N,128]
{
    __shared__ int mask[Nn];
    __shared__ float red[2][4][128];
    __shared__ float ms[4][128];
    __shared__ float pg[4][128];
    const int blk = blockIdx.x;
    const int b   = blk >> 6;
    const int j0  = (blk & 63) * 4;
    const int tid = threadIdx.x;
    const int d   = tid & 127;
    const int ih  = tid >> 7;

    {
        const int* p = adj + ((size_t)(b * Nn + tid) * Nn + j0);
        const int4 a = *(const int4*)p;
        mask[tid] = (a.x > 0) | ((a.y > 0) << 1) | ((a.z > 0) << 2) | ((a.w > 0) << 3);
    }
    __syncthreads();

    const float* m2 = g_msg2 + (size_t)(b * (Nn + 1)) * Dd + d;
    const float vv = m2[Nn * Dd];
    float vj[4] = {vv, vv, vv, vv};

#pragma unroll 4
    for (int ii = 0; ii < 128; ++ii) {
        const int i = ih * 128 + ii;
        const float x = m2[i * Dd];
        const int mk = mask[i];
#pragma unroll
        for (int q = 0; q < 4; ++q)
            if (mk & (1 << q)) vj[q] = fmaxf(vj[q], x);
    }
#pragma unroll
    for (int q = 0; q < 4; ++q) red[ih][q][d] = vj[q];
    __syncthreads();

    if (ih == 0) {
#pragma unroll
        for (int q = 0; q < 4; ++q)
            ms[q][d] = g_msg1[(size_t)(b * (Nn + 1) + j0 + q) * Dd + d]
                     + fmaxf(red[0][q][d], red[1][q][d]);
    }
    __syncthreads();

    float acc[4] = {0.f, 0.f, 0.f, 0.f};
    const int kb = ih * 64;
#pragma unroll 4
    for (int kk = 0; kk < 64; ++kk) {
        const int k = kb + kk;
        const float w = Wo2[k * Dd + d];
#pragma unroll
        for (int q = 0; q < 4; ++q) acc[q] = fmaf(ms[q][k], w, acc[q]);
    }
    if (ih) {
#pragma unroll
        for (int q = 0; q < 4; ++q) pg[q][d] = acc[q];
    }
    __syncthreads();
    if (!ih) {
        const float bb = bo2[d];
#pragma unroll
        for (int q = 0; q < 4; ++q)
            out[(size_t)(b * Nn + j0 + q) * Dd + d] =
                acc[q] + pg[q][d] + g_o1[(size_t)(b * (Nn + 1) + j0 + q) * Dd + d] + bb;
    }
}

// ===========================================================================
extern "C" void kernel_launch(void* const* d_in, const int* in_sizes, int n_in,
                              void* d_out, int out_size)
{
    const float* node_fts = (const float*)d_in[0];
    const float* edge_fts = (const float*)d_in[1];
    const int*   adj_mat  = (const int*)d_in[3];
    const float* hidden   = (const float*)d_in[4];
    const float* e_hidden = (const float*)d_in[5];
    const float* We   = (const float*)d_in[6];
    const float* be   = (const float*)d_in[7];
    const float* W_m1 = (const float*)d_in[8];
    const float* b_m1 = (const float*)d_in[9];
    const float* W_m2 = (const float*)d_in[10];
    const float* b_m2 = (const float*)d_in[11];
    const float* W_o1 = (const float*)d_in[12];
    const float* b_o1 = (const float*)d_in[13];
    const float* W_o2 = (const float*)d_in[14];
    const float* b_o2 = (const float*)d_in[15];

    float* ret_out = (float*)d_out;
    float* et_out  = (float*)d_out + Bq * Nn * Dd;

    static cudaStream_t s_chain = nullptr;
    static cudaEvent_t ev_fork = nullptr, ev_join = nullptr;
    if (!s_chain) {
        cudaStreamCreateWithFlags(&s_chain, cudaStreamNonBlocking);
        cudaEventCreateWithFlags(&ev_fork, cudaEventDisableTiming);
        cudaEventCreateWithFlags(&ev_join, cudaEventDisableTiming);
        cudaFuncSetAttribute(et_mma_kernel, cudaFuncAttributeMaxDynamicSharedMemorySize, SMEM_ET);
    }

    // fork: MPNN chain runs concurrently with the big et GEMM
    cudaEventRecord(ev_fork, 0);
    cudaStreamWaitEvent(s_chain, ev_fork, 0);
    msgs_gemm_kernel<<<NROWS / 8, 512, 0, s_chain>>>(node_fts, hidden,
                                                     W_m1, b_m1, W_m2, b_m2, W_o1, b_o1);
    maxfinal_kernel<<<Bq * Nn / 4, 256, 0, s_chain>>>(adj_mat, W_o2, b_o2, ret_out);
    cudaEventRecord(ev_join, s_chain);

    // et GEMM (k64 regions: half the barriers of R8 per unit work)
    et_mma_kernel<<<148, 512, SMEM_ET>>>(edge_fts, e_hidden, We, be, et_out);

    // join
    cudaStreamWaitEvent(0, ev_join, 0);
}